// round 1
// baseline (speedup 1.0000x reference)
#include <cuda_runtime.h>
#include <cuda_bf16.h>
#include <cstdint>

// Problem constants
#define BATCH 16
#define CIN   128
#define COUT  256
#define HW    56
#define KK    3
#define A_LEVELS 256

#define CQ    (CIN/4)        // 32 channel-quads
#define X_ELEMS (BATCH*CQ*HW*HW)     // 1,605,632 u32
#define W_ELEMS (9*CQ*COUT)          // 73,728 u32

// Scratch (device globals: no allocation allowed in kernel_launch)
__device__ unsigned g_xq[X_ELEMS];   // packed quantized activations [b][cq][h][w], u8x4 over channel quad
__device__ unsigned g_wq[W_ELEMS];   // packed quantized weights     [khkw][cq][o], u8x4 over channel quad

// ---------------------------------------------------------------------------
// Kernel 1: quantize + pack activations.
// xq = clip(rint(x*255), 0, 255); pack 4 consecutive channels into one u32.
// ---------------------------------------------------------------------------
__global__ void pack_x_kernel(const float* __restrict__ x) {
    int idx = blockIdx.x * blockDim.x + threadIdx.x;
    if (idx >= X_ELEMS) return;
    int w  = idx % HW;
    int h  = (idx / HW) % HW;
    int cq = (idx / (HW*HW)) % CQ;
    int b  = idx / (HW*HW*CQ);
    unsigned v = 0;
#pragma unroll
    for (int i = 0; i < 4; ++i) {
        int c = cq * 4 + i;
        float xv = x[((b * CIN + c) * HW + h) * HW + w];
        float q = rintf(xv * 255.0f);
        q = fminf(fmaxf(q, 0.0f), 255.0f);
        v |= ((unsigned)(int)q) << (8 * i);
    }
    g_xq[idx] = v;
}

// ---------------------------------------------------------------------------
// Kernel 2: extract qw = pcilt[...,1] and pack into [khkw][cq][o] u8x4.
// pcilt layout: [O][C][3][3][256]; qw values are exact small integers 0..255.
// ---------------------------------------------------------------------------
__global__ void pack_w_kernel(const float* __restrict__ pcilt) {
    int idx = blockIdx.x * blockDim.x + threadIdx.x;
    if (idx >= W_ELEMS) return;
    int o  = idx % COUT;
    int cq = (idx / COUT) % CQ;
    int kk = idx / (COUT * CQ);
    int kh = kk / 3, kw = kk % 3;
    unsigned v = 0;
#pragma unroll
    for (int i = 0; i < 4; ++i) {
        int c = cq * 4 + i;
        long long pidx = ((((long long)o * CIN + c) * KK + kh) * KK + kw) * A_LEVELS + 1;
        float wv = pcilt[pidx];
        v |= ((unsigned)(int)rintf(wv)) << (8 * i);
    }
    g_wq[(kk * CQ + cq) * COUT + o] = v;
}

// ---------------------------------------------------------------------------
// Kernel 3: direct 3x3 conv with dp4a (exact integer accumulation).
// Block: 224 threads. Tile: 1 batch, 32 oc, 4 output rows, full width 56.
// Thread: 8 oc x 4 contiguous pixels (one row) -> 32 int accumulators.
// C loop in 4 chunks of 8 channel-quads (32 channels).
// ---------------------------------------------------------------------------
#define TILE_H   4
#define BO       32
#define NTHREADS 224
#define CQ_CHUNK 8

__global__ void __launch_bounds__(NTHREADS)
conv_dp4a_kernel(const float* __restrict__ bias, float* __restrict__ out) {
    __shared__ unsigned s_x[CQ_CHUNK][TILE_H + 2][60];   // 6 rows x 58 used cols (halo), padded to 60
    __shared__ unsigned s_w[CQ_CHUNK][9][BO];

    const int ht  = blockIdx.x;          // 14 h-tiles
    const int oct = blockIdx.y;          // 8 oc-tiles
    const int b   = blockIdx.z;          // 16 batches
    const int h0  = ht * TILE_H;
    const int oc0 = oct * BO;

    const int t    = threadIdx.x;
    const int oc_t = t / 56;             // 0..3
    const int px   = t % 56;
    const int r    = px / 14;            // output row within tile, 0..3
    const int w0   = (px % 14) * 4;      // output col base, multiple of 4
    const int o0   = oc_t * 8;           // oc sub-base within tile

    unsigned acc[8][4];
#pragma unroll
    for (int o = 0; o < 8; ++o)
#pragma unroll
        for (int j = 0; j < 4; ++j) acc[o][j] = 0u;

#pragma unroll 1
    for (int chunk = 0; chunk < CQ / CQ_CHUNK; ++chunk) {
        const int cq0 = chunk * CQ_CHUNK;
        __syncthreads();   // protect previous iteration's smem reads

        // Stage input tile: 8 cq x 6 rows x 58 cols (with zero padding)
        for (int i = t; i < CQ_CHUNK * 6 * 58; i += NTHREADS) {
            int col = i % 58;
            int row = (i / 58) % 6;
            int cq  = i / (58 * 6);
            int h_in = h0 + row - 1;
            int w_in = col - 1;
            unsigned v = 0u;
            if (h_in >= 0 && h_in < HW && w_in >= 0 && w_in < HW)
                v = g_xq[((b * CQ + cq0 + cq) * HW + h_in) * HW + w_in];
            s_x[cq][row][col] = v;
        }
        // Stage weights: 8 cq x 9 taps x 32 oc
        for (int i = t; i < CQ_CHUNK * 9 * BO; i += NTHREADS) {
            int o  = i % BO;
            int kk = (i / BO) % 9;
            int cq = i / (BO * 9);
            s_w[cq][kk][o] = g_wq[(kk * CQ + cq0 + cq) * COUT + oc0 + o];
        }
        __syncthreads();

#pragma unroll 1
        for (int cq = 0; cq < CQ_CHUNK; ++cq) {
#pragma unroll
            for (int kh = 0; kh < 3; ++kh) {
                unsigned xr[6];
#pragma unroll
                for (int j = 0; j < 6; ++j) xr[j] = s_x[cq][r + kh][w0 + j];
#pragma unroll
                for (int kw = 0; kw < 3; ++kw) {
                    const uint4 wa = *(const uint4*)&s_w[cq][kh * 3 + kw][o0];
                    const uint4 wb = *(const uint4*)&s_w[cq][kh * 3 + kw][o0 + 4];
                    unsigned wv[8] = {wa.x, wa.y, wa.z, wa.w, wb.x, wb.y, wb.z, wb.w};
#pragma unroll
                    for (int o = 0; o < 8; ++o)
#pragma unroll
                        for (int j = 0; j < 4; ++j)
                            acc[o][j] = __dp4a(xr[kw + j], wv[o], acc[o][j]);
                }
            }
        }
    }

    // Epilogue: add bias, store as float4 (w0 multiple of 4 -> 16B aligned)
#pragma unroll
    for (int o = 0; o < 8; ++o) {
        int oc = oc0 + o0 + o;
        float bv = bias[oc];
        float4 res;
        res.x = (float)acc[o][0] + bv;
        res.y = (float)acc[o][1] + bv;
        res.z = (float)acc[o][2] + bv;
        res.w = (float)acc[o][3] + bv;
        float* dst = out + ((((long long)b * COUT + oc) * HW) + (h0 + r)) * HW + w0;
        *(float4*)dst = res;
    }
}

// ---------------------------------------------------------------------------
extern "C" void kernel_launch(void* const* d_in, const int* in_sizes, int n_in,
                              void* d_out, int out_size) {
    // Identify inputs by element count (defensive against ordering)
    const float* x = nullptr;
    const float* pcilt = nullptr;
    const float* bias = nullptr;
    for (int i = 0; i < n_in; ++i) {
        if (in_sizes[i] == COUT) bias = (const float*)d_in[i];
        else if (in_sizes[i] == BATCH * CIN * HW * HW) x = (const float*)d_in[i];
        else pcilt = (const float*)d_in[i];
    }
    float* out = (float*)d_out;

    {
        int n = X_ELEMS;
        pack_x_kernel<<<(n + 255) / 256, 256>>>(x);
    }
    {
        int n = W_ELEMS;
        pack_w_kernel<<<(n + 255) / 256, 256>>>(pcilt);
    }
    {
        dim3 grid(HW / TILE_H, COUT / BO, BATCH);  // (14, 8, 16)
        conv_dp4a_kernel<<<grid, NTHREADS>>>(bias, out);
    }
    (void)out_size;
}

// round 3
// speedup vs baseline: 1.1951x; 1.1951x over previous
#include <cuda_runtime.h>
#include <cuda_bf16.h>
#include <cstdint>

#define BATCH 16
#define CIN   128
#define COUT  256
#define HW    56

// ---------------------------------------------------------------------------
// Device scratch (u32-packed u8 data; no allocation allowed in kernel_launch)
// ---------------------------------------------------------------------------
__device__ __align__(16) unsigned g_xq4[BATCH * HW * HW * (CIN / 4)]; // NHWC u8 quantized (6.4MB)
__device__ __align__(16) unsigned g_wq4[9 * COUT * (CIN / 4)];        // [tap][o][c] u8 (294KB)

// ---------------------------------------------------------------------------
// Kernel 1: x NCHW f32 -> NHWC u8 quantized (smem transpose per (b,h) row)
// ---------------------------------------------------------------------------
__global__ void pack_x_kernel(const float* __restrict__ x) {
    __shared__ float tile[CIN][HW + 1];
    const int b = blockIdx.x / HW, h = blockIdx.x % HW;
    const int t = threadIdx.x;
    for (int i = t; i < CIN * HW; i += 256) {
        int c = i / HW, w = i % HW;
        tile[c][w] = x[((b * CIN + c) * HW + h) * HW + w];
    }
    __syncthreads();
    for (int i = t; i < HW * (CIN / 4); i += 256) {
        int w = i >> 5, cq = i & 31;
        unsigned v = 0;
#pragma unroll
        for (int k = 0; k < 4; ++k) {
            float q = rintf(tile[cq * 4 + k][w] * 255.0f);
            q = fminf(fmaxf(q, 0.0f), 255.0f);
            v |= ((unsigned)(int)q) << (8 * k);
        }
        g_xq4[((b * HW + h) * HW + w) * 32 + cq] = v;
    }
}

// ---------------------------------------------------------------------------
// Kernel 2: pcilt[...,1] -> [tap][o][c] u8 (exact integers 0..255)
// ---------------------------------------------------------------------------
__global__ void pack_w_kernel(const float* __restrict__ pcilt) {
    int idx = blockIdx.x * 256 + threadIdx.x;
    if (idx >= 9 * COUT * 32) return;
    int cq  = idx % 32;
    int o   = (idx / 32) % COUT;
    int tap = idx / (32 * COUT);
    unsigned v = 0;
#pragma unroll
    for (int k = 0; k < 4; ++k) {
        long long p = (((long long)(o * CIN + cq * 4 + k)) * 9 + tap) * 256 + 1;
        v |= ((unsigned)(int)rintf(pcilt[p])) << (8 * k);
    }
    g_wq4[(tap * COUT + o) * 32 + cq] = v;
}

// ---------------------------------------------------------------------------
// Kernel 3: u8 IMMA implicit-GEMM conv (mma.sync m16n8k32 u8*u8 -> s32).
// CTA: 1 batch, 2 out rows (M=128 = 2 x 64 padded cols), 128 oc.
// K = 128 ch per tap, 9 taps. kw/kh shift = smem address offset.
// ---------------------------------------------------------------------------
#define SX_STRIDE 144                      // bytes per pixel row (36 banks == 4 mod 32)
#define SX_ROWS   260                      // 256 tile pixels + 4 zero pad rows
#define SW_STRIDE 144
#define SMEM_SX   0
#define SMEM_SW0  (SX_ROWS * SX_STRIDE)            // 37440
#define SMEM_SW1  (SMEM_SW0 + COUT/2 * SW_STRIDE)  // 55872
#define SMEM_SZ   (SMEM_SW1 + COUT/2 * SW_STRIDE)  // 74304
#define OSTR      132                              // epilogue f32 row stride (in floats)

__device__ __forceinline__ void imma(int* c, unsigned a0, unsigned a1, unsigned a2, unsigned a3,
                                     unsigned b0, unsigned b1) {
    asm volatile(
        "mma.sync.aligned.m16n8k32.row.col.s32.u8.u8.s32 "
        "{%0,%1,%2,%3}, {%4,%5,%6,%7}, {%8,%9}, {%0,%1,%2,%3};"
        : "+r"(c[0]), "+r"(c[1]), "+r"(c[2]), "+r"(c[3])
        : "r"(a0), "r"(a1), "r"(a2), "r"(a3), "r"(b0), "r"(b1));
}

__global__ void __launch_bounds__(256)
conv_imma_kernel(const float* __restrict__ bias, float* __restrict__ out) {
    extern __shared__ __align__(16) unsigned char smem[];

    const int t    = threadIdx.x;
    const int wid  = t >> 5;
    const int lane = t & 31;
    const int h0     = blockIdx.x * 2;
    const int ocbase = blockIdx.y * 128;
    const int b      = blockIdx.z;

    // ---- Stage input tile: rows h0-1..h0+2, cols -1..62, 128 ch u8 ----
    for (int i = t; i < SX_ROWS * 8; i += 256) {
        int pixel = i >> 3, chunk = i & 7;
        int irow = pixel >> 6, col = pixel & 63;
        int h_in = h0 + irow - 1, w_in = col - 1;
        uint4 v = make_uint4(0u, 0u, 0u, 0u);
        if (pixel < 256 && h_in >= 0 && h_in < HW && w_in >= 0 && w_in < HW)
            v = *(const uint4*)&g_xq4[((b * HW + h_in) * HW + w_in) * 32 + chunk * 4];
        *(uint4*)(smem + SMEM_SX + pixel * SX_STRIDE + chunk * 16) = v;
    }
    // ---- Stage weights tap 0 -> buf0 ----
    for (int i = t; i < 128 * 8; i += 256) {
        int o = i >> 3, chunk = i & 7;
        uint4 v = *(const uint4*)&g_wq4[(0 * COUT + ocbase + o) * 32 + chunk * 4];
        *(uint4*)(smem + SMEM_SW0 + o * SW_STRIDE + chunk * 16) = v;
    }
    __syncthreads();

    const int wm = (wid >> 2) * 64;          // warp M offset (0/64)
    const int wn = (wid & 3) * 32;           // warp N offset (0/32/64/96)

    int acc[4][4][4];
#pragma unroll
    for (int mt = 0; mt < 4; ++mt)
#pragma unroll
        for (int nt = 0; nt < 4; ++nt)
#pragma unroll
            for (int k = 0; k < 4; ++k) acc[mt][nt][k] = 0;

    // Per-lane fragment base offsets
    const int a_base = (wm + (lane >> 2)) * SX_STRIDE + (lane & 3) * 4;
    const int b_base = (wn + (lane >> 2)) * SW_STRIDE + (lane & 3) * 4;

#pragma unroll 1
    for (int tap = 0; tap < 9; ++tap) {
        const int kh = tap / 3, kw = tap % 3;
        const unsigned char* swc = smem + ((tap & 1) ? SMEM_SW1 : SMEM_SW0);
        const int aoff = (kh * 64 + kw) * SX_STRIDE;

        // Prefetch next tap's weights into registers (hidden behind compute)
        uint4 wst[4];
        if (tap < 8) {
#pragma unroll
            for (int j = 0; j < 4; ++j) {
                int i = t + j * 256;
                int o = i >> 3, chunk = i & 7;
                wst[j] = *(const uint4*)&g_wq4[((tap + 1) * COUT + ocbase + o) * 32 + chunk * 4];
            }
        }

        // Compute: 4 K-steps of 32 channels
#pragma unroll
        for (int ks = 0; ks < 4; ++ks) {
            const int koff = ks * 32;
            unsigned a[4][4], bf[4][2];
#pragma unroll
            for (int mt = 0; mt < 4; ++mt) {
                const unsigned char* p = smem + SMEM_SX + a_base + aoff + mt * 16 * SX_STRIDE + koff;
                a[mt][0] = *(const unsigned*)(p);
                a[mt][1] = *(const unsigned*)(p + 8 * SX_STRIDE);
                a[mt][2] = *(const unsigned*)(p + 16);
                a[mt][3] = *(const unsigned*)(p + 8 * SX_STRIDE + 16);
            }
#pragma unroll
            for (int nt = 0; nt < 4; ++nt) {
                const unsigned char* p = swc + b_base + nt * 8 * SW_STRIDE + koff;
                bf[nt][0] = *(const unsigned*)(p);
                bf[nt][1] = *(const unsigned*)(p + 16);
            }
#pragma unroll
            for (int mt = 0; mt < 4; ++mt)
#pragma unroll
                for (int nt = 0; nt < 4; ++nt)
                    imma(acc[mt][nt], a[mt][0], a[mt][1], a[mt][2], a[mt][3],
                         bf[nt][0], bf[nt][1]);
        }

        // Store next tap's weights into the other buffer
        if (tap < 8) {
            unsigned char* swn = smem + ((tap & 1) ? SMEM_SW0 : SMEM_SW1);
#pragma unroll
            for (int j = 0; j < 4; ++j) {
                int i = t + j * 256;
                int o = i >> 3, chunk = i & 7;
                *(uint4*)(swn + o * SW_STRIDE + chunk * 16) = wst[j];
            }
        }
        __syncthreads();
    }

    // ---- Epilogue: transpose through smem -> coalesced NCHW stores ----
    float* s_out = (float*)smem;     // [128 oc][OSTR floats], reuses staging space
#pragma unroll
    for (int mt = 0; mt < 4; ++mt)
#pragma unroll
        for (int nt = 0; nt < 4; ++nt) {
            int row = wm + mt * 16 + (lane >> 2);
            int col = wn + nt * 8 + (lane & 3) * 2;
            s_out[col * OSTR + row]           = (float)acc[mt][nt][0];
            s_out[(col + 1) * OSTR + row]     = (float)acc[mt][nt][1];
            s_out[col * OSTR + row + 8]       = (float)acc[mt][nt][2];
            s_out[(col + 1) * OSTR + row + 8] = (float)acc[mt][nt][3];
        }
    __syncthreads();

    for (int i = t; i < 128 * 2 * 14; i += 256) {
        int chunk = i % 14;
        int r     = (i / 14) & 1;
        int oc    = i / 28;
        const float* sp = &s_out[oc * OSTR + r * 64 + chunk * 4];
        float bv = bias[ocbase + oc];
        float4 v = make_float4(sp[0] + bv, sp[1] + bv, sp[2] + bv, sp[3] + bv);
        float* dst = out + (((long long)b * COUT + ocbase + oc) * HW + (h0 + r)) * HW + chunk * 4;
        *(float4*)dst = v;
    }
}

// ---------------------------------------------------------------------------
extern "C" void kernel_launch(void* const* d_in, const int* in_sizes, int n_in,
                              void* d_out, int out_size) {
    const float* x = nullptr;
    const float* pcilt = nullptr;
    const float* bias = nullptr;
    for (int i = 0; i < n_in; ++i) {
        if (in_sizes[i] == COUT) bias = (const float*)d_in[i];
        else if (in_sizes[i] == BATCH * CIN * HW * HW) x = (const float*)d_in[i];
        else pcilt = (const float*)d_in[i];
    }
    float* out = (float*)d_out;

    pack_x_kernel<<<BATCH * HW, 256>>>(x);
    {
        int n = 9 * COUT * 32;
        pack_w_kernel<<<(n + 255) / 256, 256>>>(pcilt);
    }
    {
        cudaFuncSetAttribute(conv_imma_kernel,
                             cudaFuncAttributeMaxDynamicSharedMemorySize, SMEM_SZ);
        dim3 grid(HW / 2, 2, BATCH);   // (28, 2, 16) = 896 CTAs
        conv_imma_kernel<<<grid, 256, SMEM_SZ>>>(bias, out);
    }
    (void)out_size;
}

// round 4
// speedup vs baseline: 1.8944x; 1.5851x over previous
#include <cuda_runtime.h>
#include <cuda_fp16.h>
#include <cstdint>

#define BATCH 16
#define CIN   128
#define COUT  256
#define HW    56

// ---------------------------------------------------------------------------
// Device scratch (fp16; exact integers 0..255). No allocations in kernel_launch.
// ---------------------------------------------------------------------------
__device__ __align__(16) __half g_xh[BATCH * HW * HW * CIN]; // NHWC fp16 quantized (12.8MB)
__device__ __align__(16) __half g_wh[9 * COUT * CIN];        // [tap][o][c] fp16 (0.6MB)

__device__ __forceinline__ uint32_t smem_u32(const void* p) {
    uint32_t a;
    asm("{ .reg .u64 t; cvta.to.shared.u64 t, %1; cvt.u32.u64 %0, t; }" : "=r"(a) : "l"(p));
    return a;
}

// ---------------------------------------------------------------------------
// Kernel 1: x NCHW f32 -> NHWC fp16 quantized (smem transpose per (b,h) row)
// ---------------------------------------------------------------------------
__global__ void pack_x_kernel(const float* __restrict__ x) {
    __shared__ float tile[64][HW + 1];
    const int b = blockIdx.x / HW, h = blockIdx.x % HW;
    const int half_c = blockIdx.y;                 // 0/1: channel half
    const int t = threadIdx.x;
    for (int i = t; i < 64 * HW; i += 256) {
        int c = i / HW, w = i % HW;
        tile[c][w] = x[((b * CIN + half_c * 64 + c) * HW + h) * HW + w];
    }
    __syncthreads();
    for (int i = t; i < HW * 32; i += 256) {
        int w = i >> 5, cp = i & 31;               // cp: pair of channels
        float q0 = rintf(tile[cp * 2][w] * 255.0f);
        float q1 = rintf(tile[cp * 2 + 1][w] * 255.0f);
        q0 = fminf(fmaxf(q0, 0.0f), 255.0f);
        q1 = fminf(fmaxf(q1, 0.0f), 255.0f);
        __half2 v = __floats2half2_rn(q0, q1);
        *(__half2*)&g_xh[((b * HW + h) * HW + w) * CIN + half_c * 64 + cp * 2] = v;
    }
}

// ---------------------------------------------------------------------------
// Kernel 2: pcilt[...,1] -> [tap][o][c] fp16 (exact integers 0..255)
// ---------------------------------------------------------------------------
__global__ void pack_w_kernel(const float* __restrict__ pcilt) {
    int idx = blockIdx.x * 256 + threadIdx.x;
    if (idx >= 9 * COUT * CIN) return;
    int c   = idx % CIN;
    int o   = (idx / CIN) % COUT;
    int tap = idx / (CIN * COUT);
    long long p = (((long long)(o * CIN + c)) * 9 + tap) * 256 + 1;
    g_wh[(tap * COUT + o) * CIN + c] = __float2half_rn(pcilt[p]);
}

// ---------------------------------------------------------------------------
// Kernel 3: fp16 HMMA implicit-GEMM conv (mma.sync m16n8k16 f16*f16 -> f32).
// CTA: 1 batch, 2 out rows (M=128 = 2 x 64 padded cols), 128 oc.
// K = 128 ch per tap, 9 taps. kw/kh shift = smem address offset.
// ---------------------------------------------------------------------------
#define SX_STRIDE 272                      // bytes per pixel row (68 banks == 4 mod 32)
#define SX_ROWS   260                      // 258 needed (m127+kh128+kw2), +pad
#define SW_STRIDE 272
#define SMEM_SX   0
#define SMEM_SW0  (SX_ROWS * SX_STRIDE)            // 70720
#define SMEM_SW1  (SMEM_SW0 + 128 * SW_STRIDE)     // 105536
#define SMEM_SZ   (SMEM_SW1 + 128 * SW_STRIDE)     // 140352
#define OSTR      132                              // epilogue f32 row stride (floats)

__device__ __forceinline__ void hmma(float* c, unsigned a0, unsigned a1, unsigned a2, unsigned a3,
                                     unsigned b0, unsigned b1) {
    asm volatile(
        "mma.sync.aligned.m16n8k16.row.col.f32.f16.f16.f32 "
        "{%0,%1,%2,%3}, {%4,%5,%6,%7}, {%8,%9}, {%0,%1,%2,%3};"
        : "+f"(c[0]), "+f"(c[1]), "+f"(c[2]), "+f"(c[3])
        : "r"(a0), "r"(a1), "r"(a2), "r"(a3), "r"(b0), "r"(b1));
}

__global__ void __launch_bounds__(256)
conv_hmma_kernel(const float* __restrict__ bias, float* __restrict__ out) {
    extern __shared__ __align__(16) unsigned char smem[];
    const uint32_t sb = smem_u32(smem);

    const int t    = threadIdx.x;
    const int wid  = t >> 5;
    const int lane = t & 31;
    const int h0     = blockIdx.x * 2;
    const int ocbase = blockIdx.y * 128;
    const int b      = blockIdx.z;

    // ---- Stage input tile: rows h0-1..h0+2, cols -1..62, 128 ch fp16 ----
    for (int i = t; i < SX_ROWS * 16; i += 256) {
        int pixel = i >> 4, chunk = i & 15;        // chunk: 8 halves = 16B
        int irow = pixel >> 6, col = pixel & 63;
        int h_in = h0 + irow - 1, w_in = col - 1;
        uint4 v = make_uint4(0u, 0u, 0u, 0u);
        if (pixel < 256 && h_in >= 0 && h_in < HW && w_in >= 0 && w_in < HW)
            v = *(const uint4*)&g_xh[((b * HW + h_in) * HW + w_in) * CIN + chunk * 8];
        *(uint4*)(smem + SMEM_SX + pixel * SX_STRIDE + chunk * 16) = v;
    }
    // ---- Stage weights tap 0 -> buf0 via cp.async ----
    for (int i = t; i < 128 * 16; i += 256) {
        int o = i >> 4, chunk = i & 15;
        uint32_t dst = sb + SMEM_SW0 + o * SW_STRIDE + chunk * 16;
        const __half* src = &g_wh[(0 * COUT + ocbase + o) * CIN + chunk * 8];
        asm volatile("cp.async.cg.shared.global [%0], [%1], 16;" :: "r"(dst), "l"(src));
    }
    asm volatile("cp.async.commit_group;");
    asm volatile("cp.async.wait_group 0;" ::: "memory");
    __syncthreads();

    const int wm = (wid >> 2) * 64;          // warp M offset (0/64)
    const int wn = (wid & 3) * 32;           // warp N offset (0/32/64/96)

    float acc[4][4][4];
#pragma unroll
    for (int mt = 0; mt < 4; ++mt)
#pragma unroll
        for (int nt = 0; nt < 4; ++nt)
#pragma unroll
            for (int k = 0; k < 4; ++k) acc[mt][nt][k] = 0.0f;

    const int a_base = (wm + (lane >> 2)) * SX_STRIDE + (lane & 3) * 4;
    const int b_base = (wn + (lane >> 2)) * SW_STRIDE + (lane & 3) * 4;

#pragma unroll 1
    for (int tap = 0; tap < 9; ++tap) {
        const int kh = tap / 3, kw = tap % 3;
        const unsigned char* swc = smem + ((tap & 1) ? SMEM_SW1 : SMEM_SW0);
        const int aoff = (kh * 64 + kw) * SX_STRIDE;

        // Prefetch next tap's weights into the other buffer (cp.async, no regs)
        if (tap < 8) {
            uint32_t swn = sb + ((tap & 1) ? SMEM_SW0 : SMEM_SW1);
#pragma unroll
            for (int j = 0; j < 2; ++j) {
                int i = t + j * 256;               // 512 of 2048 chunks per thread pair
                int o = i >> 4, chunk = i & 15;
                // each thread does 8 chunks: stride 256 over 2048
                (void)o; (void)chunk;
            }
#pragma unroll
            for (int j = 0; j < 8; ++j) {
                int i = t + j * 256;
                int o = i >> 4, chunk = i & 15;
                uint32_t dst = swn + o * SW_STRIDE + chunk * 16;
                const __half* src = &g_wh[((tap + 1) * COUT + ocbase + o) * CIN + chunk * 8];
                asm volatile("cp.async.cg.shared.global [%0], [%1], 16;" :: "r"(dst), "l"(src));
            }
            asm volatile("cp.async.commit_group;");
        }

        // Compute: 8 K-steps of 16 channels
#pragma unroll
        for (int ks = 0; ks < 8; ++ks) {
            const int koff = ks * 32;              // 16 ch * 2B
            unsigned a[4][4], bf[4][2];
#pragma unroll
            for (int mt = 0; mt < 4; ++mt) {
                const unsigned char* p = smem + SMEM_SX + a_base + aoff + mt * 16 * SX_STRIDE + koff;
                a[mt][0] = *(const unsigned*)(p);
                a[mt][1] = *(const unsigned*)(p + 8 * SX_STRIDE);
                a[mt][2] = *(const unsigned*)(p + 16);
                a[mt][3] = *(const unsigned*)(p + 8 * SX_STRIDE + 16);
            }
#pragma unroll
            for (int nt = 0; nt < 4; ++nt) {
                const unsigned char* p = swc + b_base + nt * 8 * SW_STRIDE + koff;
                bf[nt][0] = *(const unsigned*)(p);
                bf[nt][1] = *(const unsigned*)(p + 16);
            }
#pragma unroll
            for (int mt = 0; mt < 4; ++mt)
#pragma unroll
                for (int nt = 0; nt < 4; ++nt)
                    hmma(acc[mt][nt], a[mt][0], a[mt][1], a[mt][2], a[mt][3],
                         bf[nt][0], bf[nt][1]);
        }

        if (tap < 8) asm volatile("cp.async.wait_group 0;" ::: "memory");
        __syncthreads();
    }

    // ---- Epilogue: transpose through smem -> coalesced NCHW float4 stores ----
    float* s_out = (float*)smem;
#pragma unroll
    for (int mt = 0; mt < 4; ++mt)
#pragma unroll
        for (int nt = 0; nt < 4; ++nt) {
            int row = wm + mt * 16 + (lane >> 2);
            int col = wn + nt * 8 + (lane & 3) * 2;
            s_out[col * OSTR + row]           = acc[mt][nt][0];
            s_out[(col + 1) * OSTR + row]     = acc[mt][nt][1];
            s_out[col * OSTR + row + 8]       = acc[mt][nt][2];
            s_out[(col + 1) * OSTR + row + 8] = acc[mt][nt][3];
        }
    __syncthreads();

    for (int i = t; i < 128 * 2 * 14; i += 256) {
        int chunk = i % 14;
        int r     = (i / 14) & 1;
        int oc    = i / 28;
        const float* sp = &s_out[oc * OSTR + r * 64 + chunk * 4];
        float bv = bias[ocbase + oc];
        float4 v = make_float4(sp[0] + bv, sp[1] + bv, sp[2] + bv, sp[3] + bv);
        float* dst = out + (((long long)b * COUT + ocbase + oc) * HW + (h0 + r)) * HW + chunk * 4;
        *(float4*)dst = v;
    }
}

// ---------------------------------------------------------------------------
extern "C" void kernel_launch(void* const* d_in, const int* in_sizes, int n_in,
                              void* d_out, int out_size) {
    const float* x = nullptr;
    const float* pcilt = nullptr;
    const float* bias = nullptr;
    for (int i = 0; i < n_in; ++i) {
        if (in_sizes[i] == COUT) bias = (const float*)d_in[i];
        else if (in_sizes[i] == BATCH * CIN * HW * HW) x = (const float*)d_in[i];
        else pcilt = (const float*)d_in[i];
    }
    float* out = (float*)d_out;

    {
        dim3 g(BATCH * HW, 2);
        pack_x_kernel<<<g, 256>>>(x);
    }
    {
        int n = 9 * COUT * CIN;
        pack_w_kernel<<<(n + 255) / 256, 256>>>(pcilt);
    }
    {
        cudaFuncSetAttribute(conv_hmma_kernel,
                             cudaFuncAttributeMaxDynamicSharedMemorySize, SMEM_SZ);
        dim3 grid(HW / 2, 2, BATCH);   // (28, 2, 16) = 896 CTAs
        conv_hmma_kernel<<<grid, 256, SMEM_SZ>>>(bias, out);
    }
    (void)out_size;
}

// round 5
// speedup vs baseline: 2.2296x; 1.1770x over previous
#include <cuda_runtime.h>
#include <cuda_fp16.h>
#include <cstdint>

#define BATCH 16
#define CIN   128
#define COUT  256
#define HW    56

// ---------------------------------------------------------------------------
// Device scratch (fp16 exact integers 0..255)
// ---------------------------------------------------------------------------
__device__ __align__(16) __half g_xh[BATCH * HW * HW * CIN]; // NHWC fp16 (12.8MB)
__device__ __align__(16) __half g_wh[9 * COUT * CIN];        // [tap][o][c] fp16

__device__ __forceinline__ uint32_t smem_u32(const void* p) {
    uint32_t a;
    asm("{ .reg .u64 t; cvta.to.shared.u64 t, %1; cvt.u32.u64 %0, t; }" : "=r"(a) : "l"(p));
    return a;
}

// ---------------------------------------------------------------------------
// Kernel 1: x NCHW f32 -> NHWC fp16 quantized (smem transpose, float4 loads)
// ---------------------------------------------------------------------------
__global__ void __launch_bounds__(256) pack_x_kernel(const float* __restrict__ x) {
    __shared__ float tile[CIN][60];
    const int b = blockIdx.x / HW, h = blockIdx.x % HW;
    const int t = threadIdx.x;
#pragma unroll
    for (int j = 0; j < 7; ++j) {
        int idx = t + j * 256;                 // 1792 float4 loads
        int c = idx / 14, f4 = idx % 14;
        float4 v = *(const float4*)&x[((b * CIN + c) * HW + h) * HW + f4 * 4];
        tile[c][f4 * 4 + 0] = v.x; tile[c][f4 * 4 + 1] = v.y;
        tile[c][f4 * 4 + 2] = v.z; tile[c][f4 * 4 + 3] = v.w;
    }
    __syncthreads();
    for (int i = t; i < HW * 16; i += 256) {   // 896 uint4 stores
        int w = i >> 4, chunk = i & 15;
        int c0 = chunk * 8;
        uint4 vv;
        unsigned* pv = (unsigned*)&vv;
#pragma unroll
        for (int k = 0; k < 4; ++k) {
            float q0 = rintf(tile[c0 + 2 * k][w] * 255.0f);
            float q1 = rintf(tile[c0 + 2 * k + 1][w] * 255.0f);
            q0 = fminf(fmaxf(q0, 0.0f), 255.0f);
            q1 = fminf(fmaxf(q1, 0.0f), 255.0f);
            pv[k] = __half2_raw(__floats2half2_rn(q0, q1)).x |
                    ((unsigned)__half2_raw(__floats2half2_rn(q0, q1)).y << 16);
        }
        *(uint4*)&g_xh[((b * HW + h) * HW + w) * CIN + c0] = vv;
    }
}

// ---------------------------------------------------------------------------
// Kernel 2: pcilt[...,1] -> [tap][o][c] fp16
// ---------------------------------------------------------------------------
__global__ void pack_w_kernel(const float* __restrict__ pcilt) {
    int idx = blockIdx.x * 256 + threadIdx.x;
    if (idx >= 9 * COUT * CIN) return;
    int c   = idx % CIN;
    int o   = (idx / CIN) % COUT;
    int tap = idx / (CIN * COUT);
    long long p = (((long long)(o * CIN + c)) * 9 + tap) * 256 + 1;
    g_wh[(tap * COUT + o) * CIN + c] = __float2half_rn(pcilt[p]);
}

// ---------------------------------------------------------------------------
// Kernel 3: fp16 HMMA implicit-GEMM conv, 512 threads, ldmatrix fragments.
// CTA: 1 batch, 2 out rows (M=128 = 2x64 padded cols), 128 oc. 9 taps, K=128.
// ---------------------------------------------------------------------------
#define SX_STRIDE 272                              // 68 banks == 4 mod 32
#define SX_ROWS   258
#define SW_STRIDE 272
#define SMEM_SX   0
#define SMEM_SW0  (SX_ROWS * SX_STRIDE)            // 70176
#define SMEM_SW1  (SMEM_SW0 + 128 * SW_STRIDE)     // 104992
#define SMEM_SZ   (SMEM_SW1 + 128 * SW_STRIDE)     // 139808
#define OSTR      132

__device__ __forceinline__ void hmma(float* c, unsigned a0, unsigned a1, unsigned a2, unsigned a3,
                                     unsigned b0, unsigned b1) {
    asm volatile(
        "mma.sync.aligned.m16n8k16.row.col.f32.f16.f16.f32 "
        "{%0,%1,%2,%3}, {%4,%5,%6,%7}, {%8,%9}, {%0,%1,%2,%3};"
        : "+f"(c[0]), "+f"(c[1]), "+f"(c[2]), "+f"(c[3])
        : "r"(a0), "r"(a1), "r"(a2), "r"(a3), "r"(b0), "r"(b1));
}
#define LDSM4(r0, r1, r2, r3, addr) \
    asm volatile("ldmatrix.sync.aligned.m8n8.x4.shared.b16 {%0,%1,%2,%3}, [%4];" \
        : "=r"(r0), "=r"(r1), "=r"(r2), "=r"(r3) : "r"(addr))
#define CPASYNC(dst, src, sz) \
    asm volatile("cp.async.cg.shared.global [%0], [%1], 16, %2;" :: "r"(dst), "l"(src), "r"(sz))

__global__ void __launch_bounds__(512)
conv_hmma_kernel(const float* __restrict__ bias, float* __restrict__ out) {
    extern __shared__ __align__(16) unsigned char smem[];
    const uint32_t sb = smem_u32(smem);

    const int t    = threadIdx.x;
    const int wid  = t >> 5;
    const int lane = t & 31;
    const int h0     = blockIdx.x * 2;
    const int ocbase = blockIdx.y * 128;
    const int b      = blockIdx.z;

    // ---- Stage A (cp.async, zero-fill pads via src-size 0) ----
    for (int i = t; i < SX_ROWS * 16; i += 512) {
        int pixel = i >> 4, chunk = i & 15;
        int irow = pixel >> 6, col = pixel & 63;
        int h_in = h0 + irow - 1, w_in = col - 1;
        bool ok = (pixel < 256) && (h_in >= 0) && (h_in < HW) && (w_in >= 0) && (w_in < HW);
        const __half* src = ok ? &g_xh[((b * HW + h_in) * HW + w_in) * CIN + chunk * 8] : g_xh;
        CPASYNC(sb + SMEM_SX + pixel * SX_STRIDE + chunk * 16, src, ok ? 16 : 0);
    }
    // ---- Stage B tap 0 -> buf0 ----
    for (int i = t; i < 128 * 16; i += 512) {
        int o = i >> 4, chunk = i & 15;
        CPASYNC(sb + SMEM_SW0 + o * SW_STRIDE + chunk * 16,
                &g_wh[(0 * COUT + ocbase + o) * CIN + chunk * 8], 16);
    }
    asm volatile("cp.async.commit_group;");
    asm volatile("cp.async.wait_group 0;" ::: "memory");
    __syncthreads();

    const int wm = (wid >> 2) * 32;          // 4 M-blocks of 32
    const int wn = (wid & 3) * 32;           // 4 N-blocks of 32

    float acc[2][4][4];
#pragma unroll
    for (int mt = 0; mt < 2; ++mt)
#pragma unroll
        for (int nt = 0; nt < 4; ++nt)
#pragma unroll
            for (int k = 0; k < 4; ++k) acc[mt][nt][k] = 0.0f;

    // Per-lane ldmatrix offsets
    const int g = lane >> 3;
    const int a_lane = (((g & 1) * 8) + (lane & 7)) * SX_STRIDE + (g >> 1) * 16;
    const int b_lane = (((g >> 1) * 8) + (lane & 7)) * SW_STRIDE + (g & 1) * 16;

#pragma unroll 1
    for (int tap = 0; tap < 9; ++tap) {
        const int kh = tap / 3, kw = tap % 3;
        const uint32_t swc = sb + ((tap & 1) ? SMEM_SW1 : SMEM_SW0);
        const uint32_t abase = sb + SMEM_SX + (kh * 64 + kw) * SX_STRIDE + wm * SX_STRIDE + a_lane;
        const uint32_t bbase = swc + wn * SW_STRIDE + b_lane;

        // Prefetch next tap's weights (cp.async, other buffer)
        if (tap < 8) {
            uint32_t swn = sb + ((tap & 1) ? SMEM_SW0 : SMEM_SW1);
#pragma unroll
            for (int j = 0; j < 4; ++j) {
                int i = t + j * 512;
                int o = i >> 4, chunk = i & 15;
                CPASYNC(swn + o * SW_STRIDE + chunk * 16,
                        &g_wh[((tap + 1) * COUT + ocbase + o) * CIN + chunk * 8], 16);
            }
            asm volatile("cp.async.commit_group;");
        }

#pragma unroll
        for (int ks = 0; ks < 8; ++ks) {
            const int koff = ks * 32;
            unsigned a[2][4], bf[4][2];
            LDSM4(a[0][0], a[0][1], a[0][2], a[0][3], abase + koff);
            LDSM4(a[1][0], a[1][1], a[1][2], a[1][3], abase + 16 * SX_STRIDE + koff);
            LDSM4(bf[0][0], bf[0][1], bf[1][0], bf[1][1], bbase + koff);
            LDSM4(bf[2][0], bf[2][1], bf[3][0], bf[3][1], bbase + 16 * SW_STRIDE + koff);
#pragma unroll
            for (int mt = 0; mt < 2; ++mt)
#pragma unroll
                for (int nt = 0; nt < 4; ++nt)
                    hmma(acc[mt][nt], a[mt][0], a[mt][1], a[mt][2], a[mt][3],
                         bf[nt][0], bf[nt][1]);
        }

        if (tap < 8) asm volatile("cp.async.wait_group 0;" ::: "memory");
        __syncthreads();
    }

    // ---- Epilogue: transpose via smem -> coalesced NCHW float4 stores ----
    float* s_out = (float*)smem;    // [128 oc][OSTR]
#pragma unroll
    for (int mt = 0; mt < 2; ++mt)
#pragma unroll
        for (int nt = 0; nt < 4; ++nt) {
            int row = wm + mt * 16 + (lane >> 2);
            int col = wn + nt * 8 + (lane & 3) * 2;
            s_out[col * OSTR + row]           = acc[mt][nt][0];
            s_out[(col + 1) * OSTR + row]     = acc[mt][nt][1];
            s_out[col * OSTR + row + 8]       = acc[mt][nt][2];
            s_out[(col + 1) * OSTR + row + 8] = acc[mt][nt][3];
        }
    __syncthreads();

#pragma unroll
    for (int j = 0; j < 7; ++j) {
        int i = t + j * 512;                 // 3584 = 128oc * 2rows * 14 float4
        int chunk = i % 14;
        int r     = (i / 14) & 1;
        int oc    = i / 28;
        const float* sp = &s_out[oc * OSTR + r * 64 + chunk * 4];
        float bv = bias[ocbase + oc];
        float4 v = make_float4(sp[0] + bv, sp[1] + bv, sp[2] + bv, sp[3] + bv);
        float* dst = out + (((long long)b * COUT + ocbase + oc) * HW + (h0 + r)) * HW + chunk * 4;
        *(float4*)dst = v;
    }
}

// ---------------------------------------------------------------------------
extern "C" void kernel_launch(void* const* d_in, const int* in_sizes, int n_in,
                              void* d_out, int out_size) {
    const float* x = nullptr;
    const float* pcilt = nullptr;
    const float* bias = nullptr;
    for (int i = 0; i < n_in; ++i) {
        if (in_sizes[i] == COUT) bias = (const float*)d_in[i];
        else if (in_sizes[i] == BATCH * CIN * HW * HW) x = (const float*)d_in[i];
        else pcilt = (const float*)d_in[i];
    }
    float* out = (float*)d_out;

    pack_x_kernel<<<BATCH * HW, 256>>>(x);
    {
        int n = 9 * COUT * CIN;
        pack_w_kernel<<<(n + 255) / 256, 256>>>(pcilt);
    }
    {
        cudaFuncSetAttribute(conv_hmma_kernel,
                             cudaFuncAttributeMaxDynamicSharedMemorySize, SMEM_SZ);
        dim3 grid(HW / 2, 2, BATCH);   // (28, 2, 16) = 896 CTAs
        conv_hmma_kernel<<<grid, 512, SMEM_SZ>>>(bias, out);
    }
    (void)out_size;
}

// round 6
// speedup vs baseline: 2.3442x; 1.0514x over previous
#include <cuda_runtime.h>
#include <cuda_fp16.h>
#include <cstdint>

#define BATCH 16
#define CIN   128
#define COUT  256
#define HW    56

__device__ __align__(16) __half g_xh[BATCH * HW * HW * CIN]; // NHWC fp16 (12.8MB)
__device__ __align__(16) __half g_wh[9 * COUT * CIN];        // [tap][o][c] fp16

__device__ __forceinline__ uint32_t smem_u32(const void* p) {
    uint32_t a;
    asm("{ .reg .u64 t; cvta.to.shared.u64 t, %1; cvt.u32.u64 %0, t; }" : "=r"(a) : "l"(p));
    return a;
}

// ---------------------------------------------------------------------------
// Kernel 1: x NCHW f32 -> NHWC fp16 quantized. w-major quantize loop ->
// conflict-free smem reads (consecutive lanes hit consecutive banks).
// ---------------------------------------------------------------------------
__global__ void __launch_bounds__(256) pack_x_kernel(const float* __restrict__ x) {
    __shared__ float tile[CIN][60];
    const int b = blockIdx.x / HW, h = blockIdx.x % HW;
    const int t = threadIdx.x;
#pragma unroll
    for (int j = 0; j < 7; ++j) {
        int idx = t + j * 256;                 // 1792 float4 loads
        int c = idx / 14, f4 = idx % 14;
        float4 v = *(const float4*)&x[((b * CIN + c) * HW + h) * HW + f4 * 4];
        tile[c][f4 * 4 + 0] = v.x; tile[c][f4 * 4 + 1] = v.y;
        tile[c][f4 * 4 + 2] = v.z; tile[c][f4 * 4 + 3] = v.w;
    }
    __syncthreads();
#pragma unroll
    for (int j = 0; j < 4; ++j) {              // 896 = 16 chunks * 56 w, w-major
        int i = t + j * 256;
        if (i >= HW * 16) break;
        int chunk = i / HW, w = i % HW;
        int c0 = chunk * 8;
        uint4 vv;
        unsigned* pv = (unsigned*)&vv;
#pragma unroll
        for (int k = 0; k < 4; ++k) {
            float q0 = rintf(tile[c0 + 2 * k][w] * 255.0f);
            float q1 = rintf(tile[c0 + 2 * k + 1][w] * 255.0f);
            q0 = fminf(fmaxf(q0, 0.0f), 255.0f);
            q1 = fminf(fmaxf(q1, 0.0f), 255.0f);
            __half2 h2 = __floats2half2_rn(q0, q1);
            pv[k] = *(unsigned*)&h2;
        }
        *(uint4*)&g_xh[((b * HW + h) * HW + w) * CIN + c0] = vv;
    }
}

// ---------------------------------------------------------------------------
// Kernel 2: pcilt[...,1] -> [tap][o][c] fp16
// ---------------------------------------------------------------------------
__global__ void pack_w_kernel(const float* __restrict__ pcilt) {
    int idx = blockIdx.x * 256 + threadIdx.x;
    if (idx >= 9 * COUT * CIN) return;
    int c   = idx % CIN;
    int o   = (idx / CIN) % COUT;
    int tap = idx / (CIN * COUT);
    long long p = (((long long)(o * CIN + c)) * 9 + tap) * 256 + 1;
    g_wh[(tap * COUT + o) * CIN + c] = __float2half_rn(pcilt[p]);
}

// ---------------------------------------------------------------------------
// Kernel 3: fp16 HMMA implicit-GEMM conv, 256 threads (8 warps), warp tile
// 32x64 -> LDSM traffic 1536 cyc/tap < tensor 2048 cyc/tap (tensor-bound).
// CTA: 1 batch, 2 out rows (M=128 = 2x64 padded cols), 128 oc. 9 taps, K=128.
// ---------------------------------------------------------------------------
#define SX_STRIDE 272                              // 68 banks == 4 mod 32
#define SX_ROWS   258
#define SW_STRIDE 272
#define SMEM_SX   0
#define SMEM_SW0  (SX_ROWS * SX_STRIDE)            // 70176
#define SMEM_SW1  (SMEM_SW0 + 128 * SW_STRIDE)
#define SMEM_SZ   (SMEM_SW1 + 128 * SW_STRIDE)     // 139808
#define OSTR      132

__device__ __forceinline__ void hmma(float* c, unsigned a0, unsigned a1, unsigned a2, unsigned a3,
                                     unsigned b0, unsigned b1) {
    asm volatile(
        "mma.sync.aligned.m16n8k16.row.col.f32.f16.f16.f32 "
        "{%0,%1,%2,%3}, {%4,%5,%6,%7}, {%8,%9}, {%0,%1,%2,%3};"
        : "+f"(c[0]), "+f"(c[1]), "+f"(c[2]), "+f"(c[3])
        : "r"(a0), "r"(a1), "r"(a2), "r"(a3), "r"(b0), "r"(b1));
}
#define LDSM4(r0, r1, r2, r3, addr) \
    asm volatile("ldmatrix.sync.aligned.m8n8.x4.shared.b16 {%0,%1,%2,%3}, [%4];" \
        : "=r"(r0), "=r"(r1), "=r"(r2), "=r"(r3) : "r"(addr))
#define CPASYNC(dst, src, sz) \
    asm volatile("cp.async.cg.shared.global [%0], [%1], 16, %2;" :: "r"(dst), "l"(src), "r"(sz))

__global__ void __launch_bounds__(256)
conv_hmma_kernel(const float* __restrict__ bias, float* __restrict__ out) {
    extern __shared__ __align__(16) unsigned char smem[];
    const uint32_t sb = smem_u32(smem);

    const int t    = threadIdx.x;
    const int wid  = t >> 5;
    const int lane = t & 31;
    const int h0     = blockIdx.x * 2;
    const int ocbase = blockIdx.y * 128;
    const int b      = blockIdx.z;

    // ---- Stage A (cp.async, zero-fill pads via src-size 0) ----
    for (int i = t; i < SX_ROWS * 16; i += 256) {
        int pixel = i >> 4, chunk = i & 15;
        int irow = pixel >> 6, col = pixel & 63;
        int h_in = h0 + irow - 1, w_in = col - 1;
        bool ok = (pixel < 256) && (h_in >= 0) && (h_in < HW) && (w_in >= 0) && (w_in < HW);
        const __half* src = ok ? &g_xh[((b * HW + h_in) * HW + w_in) * CIN + chunk * 8] : g_xh;
        CPASYNC(sb + SMEM_SX + pixel * SX_STRIDE + chunk * 16, src, ok ? 16 : 0);
    }
    // ---- Stage B tap 0 -> buf0 ----
    for (int i = t; i < 128 * 16; i += 256) {
        int o = i >> 4, chunk = i & 15;
        CPASYNC(sb + SMEM_SW0 + o * SW_STRIDE + chunk * 16,
                &g_wh[(0 * COUT + ocbase + o) * CIN + chunk * 8], 16);
    }
    asm volatile("cp.async.commit_group;");
    asm volatile("cp.async.wait_group 0;" ::: "memory");
    __syncthreads();

    const int wm = (wid >> 1) * 32;          // 4 M-blocks of 32 rows
    const int wn = (wid & 1) * 64;           // 2 N-blocks of 64 oc

    float acc[2][8][4];
#pragma unroll
    for (int mt = 0; mt < 2; ++mt)
#pragma unroll
        for (int nt = 0; nt < 8; ++nt)
#pragma unroll
            for (int k = 0; k < 4; ++k) acc[mt][nt][k] = 0.0f;

    const int g = lane >> 3;
    const int a_lane = (((g & 1) * 8) + (lane & 7)) * SX_STRIDE + (g >> 1) * 16;
    const int b_lane = (((g >> 1) * 8) + (lane & 7)) * SW_STRIDE + (g & 1) * 16;

#pragma unroll 1
    for (int tap = 0; tap < 9; ++tap) {
        const int kh = tap / 3, kw = tap % 3;
        const uint32_t swc = sb + ((tap & 1) ? SMEM_SW1 : SMEM_SW0);
        const uint32_t abase = sb + SMEM_SX + (kh * 64 + kw + wm) * SX_STRIDE + a_lane;
        const uint32_t bbase = swc + wn * SW_STRIDE + b_lane;

        if (tap < 8) {
            uint32_t swn = sb + ((tap & 1) ? SMEM_SW0 : SMEM_SW1);
#pragma unroll
            for (int j = 0; j < 8; ++j) {
                int i = t + j * 256;
                int o = i >> 4, chunk = i & 15;
                CPASYNC(swn + o * SW_STRIDE + chunk * 16,
                        &g_wh[((tap + 1) * COUT + ocbase + o) * CIN + chunk * 8], 16);
            }
            asm volatile("cp.async.commit_group;");
        }

#pragma unroll
        for (int ks = 0; ks < 8; ++ks) {
            const int koff = ks * 32;
            unsigned a[2][4], bf[8][2];
            LDSM4(a[0][0], a[0][1], a[0][2], a[0][3], abase + koff);
            LDSM4(a[1][0], a[1][1], a[1][2], a[1][3], abase + 16 * SX_STRIDE + koff);
#pragma unroll
            for (int q = 0; q < 4; ++q)
                LDSM4(bf[2 * q][0], bf[2 * q][1], bf[2 * q + 1][0], bf[2 * q + 1][1],
                      bbase + q * 16 * SW_STRIDE + koff);
#pragma unroll
            for (int mt = 0; mt < 2; ++mt)
#pragma unroll
                for (int nt = 0; nt < 8; ++nt)
                    hmma(acc[mt][nt], a[mt][0], a[mt][1], a[mt][2], a[mt][3],
                         bf[nt][0], bf[nt][1]);
        }

        if (tap < 8) asm volatile("cp.async.wait_group 0;" ::: "memory");
        __syncthreads();
    }

    // ---- Epilogue: transpose via smem -> coalesced NCHW float4 stores ----
    float* s_out = (float*)smem;    // [128 oc][OSTR], reuses A region
#pragma unroll
    for (int mt = 0; mt < 2; ++mt)
#pragma unroll
        for (int nt = 0; nt < 8; ++nt) {
            int row = wm + mt * 16 + (lane >> 2);
            int col = wn + nt * 8 + (lane & 3) * 2;
            s_out[col * OSTR + row]           = acc[mt][nt][0];
            s_out[(col + 1) * OSTR + row]     = acc[mt][nt][1];
            s_out[col * OSTR + row + 8]       = acc[mt][nt][2];
            s_out[(col + 1) * OSTR + row + 8] = acc[mt][nt][3];
        }
    __syncthreads();

#pragma unroll
    for (int j = 0; j < 14; ++j) {
        int i = t + j * 256;                 // 3584 = 128oc * 2rows * 14 float4
        int chunk = i % 14;
        int r     = (i / 14) & 1;
        int oc    = i / 28;
        const float* sp = &s_out[oc * OSTR + r * 64 + chunk * 4];
        float bv = bias[ocbase + oc];
        float4 v = make_float4(sp[0] + bv, sp[1] + bv, sp[2] + bv, sp[3] + bv);
        float* dst = out + (((long long)b * COUT + ocbase + oc) * HW + (h0 + r)) * HW + chunk * 4;
        *(float4*)dst = v;
    }
}

// ---------------------------------------------------------------------------
extern "C" void kernel_launch(void* const* d_in, const int* in_sizes, int n_in,
                              void* d_out, int out_size) {
    const float* x = nullptr;
    const float* pcilt = nullptr;
    const float* bias = nullptr;
    for (int i = 0; i < n_in; ++i) {
        if (in_sizes[i] == COUT) bias = (const float*)d_in[i];
        else if (in_sizes[i] == BATCH * CIN * HW * HW) x = (const float*)d_in[i];
        else pcilt = (const float*)d_in[i];
    }
    float* out = (float*)d_out;

    pack_x_kernel<<<BATCH * HW, 256>>>(x);
    {
        int n = 9 * COUT * CIN;
        pack_w_kernel<<<(n + 255) / 256, 256>>>(pcilt);
    }
    {
        cudaFuncSetAttribute(conv_hmma_kernel,
                             cudaFuncAttributeMaxDynamicSharedMemorySize, SMEM_SZ);
        dim3 grid(HW / 2, 2, BATCH);   // (28, 2, 16) = 896 CTAs
        conv_hmma_kernel<<<grid, 256, SMEM_SZ>>>(bias, out);
    }
    (void)out_size;
}

// round 7
// speedup vs baseline: 2.5393x; 1.0832x over previous
#include <cuda_runtime.h>
#include <cuda_fp16.h>
#include <cstdint>

#define BATCH 16
#define CIN   128
#define COUT  256
#define HW    56

__device__ __align__(16) __half g_xh[BATCH * HW * HW * CIN]; // NHWC fp16 (12.8MB)
__device__ __align__(16) __half g_wh[9 * COUT * CIN];        // [tap][o][c] fp16

__device__ __forceinline__ uint32_t smem_u32(const void* p) {
    uint32_t a;
    asm("{ .reg .u64 t; cvta.to.shared.u64 t, %1; cvt.u32.u64 %0, t; }" : "=r"(a) : "l"(p));
    return a;
}

// ---------------------------------------------------------------------------
// Kernel 1: x NCHW f32 -> NHWC fp16 quantized (smem transpose)
// ---------------------------------------------------------------------------
__global__ void __launch_bounds__(256) pack_x_kernel(const float* __restrict__ x) {
    __shared__ float tile[CIN][60];
    const int b = blockIdx.x / HW, h = blockIdx.x % HW;
    const int t = threadIdx.x;
#pragma unroll
    for (int j = 0; j < 7; ++j) {
        int idx = t + j * 256;
        int c = idx / 14, f4 = idx % 14;
        float4 v = *(const float4*)&x[((b * CIN + c) * HW + h) * HW + f4 * 4];
        tile[c][f4 * 4 + 0] = v.x; tile[c][f4 * 4 + 1] = v.y;
        tile[c][f4 * 4 + 2] = v.z; tile[c][f4 * 4 + 3] = v.w;
    }
    __syncthreads();
#pragma unroll
    for (int j = 0; j < 4; ++j) {
        int i = t + j * 256;
        if (i >= HW * 16) break;
        int chunk = i / HW, w = i % HW;
        int c0 = chunk * 8;
        uint4 vv;
        unsigned* pv = (unsigned*)&vv;
#pragma unroll
        for (int k = 0; k < 4; ++k) {
            float q0 = rintf(tile[c0 + 2 * k][w] * 255.0f);
            float q1 = rintf(tile[c0 + 2 * k + 1][w] * 255.0f);
            q0 = fminf(fmaxf(q0, 0.0f), 255.0f);
            q1 = fminf(fmaxf(q1, 0.0f), 255.0f);
            __half2 h2 = __floats2half2_rn(q0, q1);
            pv[k] = *(unsigned*)&h2;
        }
        *(uint4*)&g_xh[((b * HW + h) * HW + w) * CIN + c0] = vv;
    }
}

// ---------------------------------------------------------------------------
// Kernel 2: pcilt[...,1] -> [tap][o][c] fp16
// ---------------------------------------------------------------------------
__global__ void pack_w_kernel(const float* __restrict__ pcilt) {
    int idx = blockIdx.x * 256 + threadIdx.x;
    if (idx >= 9 * COUT * CIN) return;
    int c   = idx % CIN;
    int o   = (idx / CIN) % COUT;
    int tap = idx / (CIN * COUT);
    long long p = (((long long)(o * CIN + c)) * 9 + tap) * 256 + 1;
    g_wh[(tap * COUT + o) * CIN + c] = __float2half_rn(pcilt[p]);
}

// ---------------------------------------------------------------------------
// Kernel 3: fp16 HMMA implicit-GEMM conv, 8 warps (32x64 warp tiles),
// 4-slot mbarrier-pipelined weight ring — NO __syncthreads in the mainloop.
// ---------------------------------------------------------------------------
#define SX_STRIDE 272
#define SX_ROWS   258
#define SW_STRIDE 272
#define SMEM_SX   0
#define SMEM_W0   (SX_ROWS * SX_STRIDE)            // 70176
#define W_SLOT_SZ (128 * SW_STRIDE)                // 34816
#define SMEM_MB   (SMEM_W0 + 4 * W_SLOT_SZ)        // 209440 (full[4] then empty[4])
#define SMEM_SZ   (SMEM_MB + 64)
#define OSTR      132

__device__ __forceinline__ void hmma(float* c, unsigned a0, unsigned a1, unsigned a2, unsigned a3,
                                     unsigned b0, unsigned b1) {
    asm volatile(
        "mma.sync.aligned.m16n8k16.row.col.f32.f16.f16.f32 "
        "{%0,%1,%2,%3}, {%4,%5,%6,%7}, {%8,%9}, {%0,%1,%2,%3};"
        : "+f"(c[0]), "+f"(c[1]), "+f"(c[2]), "+f"(c[3])
        : "r"(a0), "r"(a1), "r"(a2), "r"(a3), "r"(b0), "r"(b1));
}
#define LDSM4(r0, r1, r2, r3, addr) \
    asm volatile("ldmatrix.sync.aligned.m8n8.x4.shared.b16 {%0,%1,%2,%3}, [%4];" \
        : "=r"(r0), "=r"(r1), "=r"(r2), "=r"(r3) : "r"(addr))
#define CPASYNC(dst, src, sz) \
    asm volatile("cp.async.cg.shared.global [%0], [%1], 16, %2;" :: "r"(dst), "l"(src), "r"(sz))
#define MBAR_INIT(a, n) asm volatile("mbarrier.init.shared.b64 [%0], %1;" :: "r"(a), "r"(n) : "memory")
#define MBAR_ARRIVE(a)  asm volatile("mbarrier.arrive.shared.b64 _, [%0];" :: "r"(a) : "memory")
#define CP_MBAR_ARRIVE(a) \
    asm volatile("cp.async.mbarrier.arrive.noinc.shared.b64 [%0];" :: "r"(a) : "memory")
#define MBAR_WAIT(a, ph) do {                                                     \
    uint32_t _m = (a), _p = (uint32_t)(ph), _d;                                   \
    asm volatile("{ .reg .pred p; mbarrier.try_wait.parity.acquire.cta.shared::cta.b64 p, [%1], %2; selp.b32 %0,1,0,p; }" \
        : "=r"(_d) : "r"(_m), "r"(_p) : "memory");                                \
    if (!_d) {                                                                    \
        asm volatile("{ .reg .pred P1; WL_%=: mbarrier.try_wait.parity.acquire.cta.shared::cta.b64 P1, [%0], %1, 0x989680;" \
            " @P1 bra.uni WD_%=; bra.uni WL_%=; WD_%=: }" :: "r"(_m), "r"(_p) : "memory"); \
    } } while (0)

__global__ void __launch_bounds__(256)
conv_hmma_kernel(const float* __restrict__ bias, float* __restrict__ out) {
    extern __shared__ __align__(16) unsigned char smem[];
    const uint32_t sb = smem_u32(smem);

    const int t    = threadIdx.x;
    const int wid  = t >> 5;
    const int lane = t & 31;
    const int h0     = blockIdx.x * 2;
    const int ocbase = blockIdx.y * 128;
    const int b      = blockIdx.z;

    const uint32_t mb_full  = sb + SMEM_MB;        // 4 x 8B
    const uint32_t mb_empty = sb + SMEM_MB + 32;   // 4 x 8B

    if (t == 0) {
#pragma unroll
        for (int s = 0; s < 4; ++s) {
            MBAR_INIT(mb_full + s * 8, 256);
            MBAR_INIT(mb_empty + s * 8, 256);
        }
    }
    __syncthreads();

    // ---- Prologue: A tile + W taps 0,1,2 into slots 0,1,2 ----
    for (int i = t; i < SX_ROWS * 16; i += 256) {
        int pixel = i >> 4, chunk = i & 15;
        int irow = pixel >> 6, col = pixel & 63;
        int h_in = h0 + irow - 1, w_in = col - 1;
        bool ok = (pixel < 256) && (h_in >= 0) && (h_in < HW) && (w_in >= 0) && (w_in < HW);
        const __half* src = ok ? &g_xh[((b * HW + h_in) * HW + w_in) * CIN + chunk * 8] : g_xh;
        CPASYNC(sb + SMEM_SX + pixel * SX_STRIDE + chunk * 16, src, ok ? 16 : 0);
    }
#pragma unroll
    for (int tap = 0; tap < 3; ++tap) {
        uint32_t wdst = sb + SMEM_W0 + tap * W_SLOT_SZ;
#pragma unroll
        for (int j = 0; j < 8; ++j) {
            int i = t + j * 256;
            int o = i >> 4, chunk = i & 15;
            CPASYNC(wdst + o * SW_STRIDE + chunk * 16,
                    &g_wh[(tap * COUT + ocbase + o) * CIN + chunk * 8], 16);
        }
        CP_MBAR_ARRIVE(mb_full + tap * 8);
    }

    const int wm = (wid >> 1) * 32;
    const int wn = (wid & 1) * 64;

    float acc[2][8][4];
#pragma unroll
    for (int mt = 0; mt < 2; ++mt)
#pragma unroll
        for (int nt = 0; nt < 8; ++nt)
#pragma unroll
            for (int k = 0; k < 4; ++k) acc[mt][nt][k] = 0.0f;

    const int g = lane >> 3;
    const int a_lane = (((g & 1) * 8) + (lane & 7)) * SX_STRIDE + (g >> 1) * 16;
    const int b_lane = (((g >> 1) * 8) + (lane & 7)) * SW_STRIDE + (g & 1) * 16;

#pragma unroll 1
    for (int tap = 0; tap < 9; ++tap) {
        const int kh = tap / 3, kw = tap % 3;
        const int slot = tap & 3;
        const uint32_t swc = sb + SMEM_W0 + slot * W_SLOT_SZ;
        const uint32_t abase = sb + SMEM_SX + (kh * 64 + kw + wm) * SX_STRIDE + a_lane;
        const uint32_t bbase = swc + wn * SW_STRIDE + b_lane;

        // Wait for this tap's weights (and, at tap 0, the A tile)
        MBAR_WAIT(mb_full + slot * 8, (tap >> 2) & 1);

#pragma unroll
        for (int ks = 0; ks < 8; ++ks) {
            const int koff = ks * 32;
            unsigned a[2][4], bf[8][2];
            LDSM4(a[0][0], a[0][1], a[0][2], a[0][3], abase + koff);
            LDSM4(a[1][0], a[1][1], a[1][2], a[1][3], abase + 16 * SX_STRIDE + koff);
#pragma unroll
            for (int q = 0; q < 4; ++q)
                LDSM4(bf[2 * q][0], bf[2 * q][1], bf[2 * q + 1][0], bf[2 * q + 1][1],
                      bbase + q * 16 * SW_STRIDE + koff);
#pragma unroll
            for (int mt = 0; mt < 2; ++mt)
#pragma unroll
                for (int nt = 0; nt < 8; ++nt)
                    hmma(acc[mt][nt], a[mt][0], a[mt][1], a[mt][2], a[mt][3],
                         bf[nt][0], bf[nt][1]);
        }

        // Signal: this thread finished reading slot
        MBAR_ARRIVE(mb_empty + slot * 8);

        // Prefetch tap+3 into slot (tap+3)%4 (the slot read at tap-1)
        if (tap <= 5) {
            const int ws = (tap + 3) & 3;
            if (tap >= 1) MBAR_WAIT(mb_empty + ws * 8, (tap == 5) ? 1 : 0);
            uint32_t wdst = sb + SMEM_W0 + ws * W_SLOT_SZ;
#pragma unroll
            for (int j = 0; j < 8; ++j) {
                int i = t + j * 256;
                int o = i >> 4, chunk = i & 15;
                CPASYNC(wdst + o * SW_STRIDE + chunk * 16,
                        &g_wh[((tap + 3) * COUT + ocbase + o) * CIN + chunk * 8], 16);
            }
            CP_MBAR_ARRIVE(mb_full + ws * 8);
        }
    }

    __syncthreads();   // all warps done with A region before epilogue reuse

    // ---- Epilogue: transpose via smem -> coalesced NCHW float4 stores ----
    float* s_out = (float*)smem;
#pragma unroll
    for (int mt = 0; mt < 2; ++mt)
#pragma unroll
        for (int nt = 0; nt < 8; ++nt) {
            int row = wm + mt * 16 + (lane >> 2);
            int col = wn + nt * 8 + (lane & 3) * 2;
            s_out[col * OSTR + row]           = acc[mt][nt][0];
            s_out[(col + 1) * OSTR + row]     = acc[mt][nt][1];
            s_out[col * OSTR + row + 8]       = acc[mt][nt][2];
            s_out[(col + 1) * OSTR + row + 8] = acc[mt][nt][3];
        }
    __syncthreads();

#pragma unroll
    for (int j = 0; j < 14; ++j) {
        int i = t + j * 256;
        int chunk = i % 14;
        int r     = (i / 14) & 1;
        int oc    = i / 28;
        const float* sp = &s_out[oc * OSTR + r * 64 + chunk * 4];
        float bv = bias[ocbase + oc];
        float4 v = make_float4(sp[0] + bv, sp[1] + bv, sp[2] + bv, sp[3] + bv);
        float* dst = out + (((long long)b * COUT + ocbase + oc) * HW + (h0 + r)) * HW + chunk * 4;
        *(float4*)dst = v;
    }
}

// ---------------------------------------------------------------------------
extern "C" void kernel_launch(void* const* d_in, const int* in_sizes, int n_in,
                              void* d_out, int out_size) {
    const float* x = nullptr;
    const float* pcilt = nullptr;
    const float* bias = nullptr;
    for (int i = 0; i < n_in; ++i) {
        if (in_sizes[i] == COUT) bias = (const float*)d_in[i];
        else if (in_sizes[i] == BATCH * CIN * HW * HW) x = (const float*)d_in[i];
        else pcilt = (const float*)d_in[i];
    }
    float* out = (float*)d_out;

    pack_x_kernel<<<BATCH * HW, 256>>>(x);
    {
        int n = 9 * COUT * CIN;
        pack_w_kernel<<<(n + 255) / 256, 256>>>(pcilt);
    }
    {
        cudaFuncSetAttribute(conv_hmma_kernel,
                             cudaFuncAttributeMaxDynamicSharedMemorySize, SMEM_SZ);
        dim3 grid(HW / 2, 2, BATCH);   // (28, 2, 16) = 896 CTAs
        conv_hmma_kernel<<<grid, 256, SMEM_SZ>>>(bias, out);
    }
    (void)out_size;
}

// round 8
// speedup vs baseline: 2.5992x; 1.0236x over previous
#include <cuda_runtime.h>
#include <cuda_fp16.h>
#include <cstdint>

#define BATCH 16
#define CIN   128
#define COUT  256
#define HW    56

__device__ __align__(16) __half g_xh[BATCH * HW * HW * CIN]; // NHWC fp16 (12.8MB)
__device__ __align__(16) __half g_wh[9 * COUT * CIN];        // [tap][o][c] fp16

__device__ __forceinline__ uint32_t smem_u32(const void* p) {
    uint32_t a;
    asm("{ .reg .u64 t; cvta.to.shared.u64 t, %1; cvt.u32.u64 %0, t; }" : "=r"(a) : "l"(p));
    return a;
}

// ---------------------------------------------------------------------------
// Kernel 1: x NCHW f32 -> NHWC fp16 quantized. 2 CTAs per (b,h): 64 ch each.
// w-major quantize loop -> conflict-free smem reads; uint4 stores.
// ---------------------------------------------------------------------------
__global__ void __launch_bounds__(256) pack_x_kernel(const float* __restrict__ x) {
    __shared__ float tile[64][60];
    const int b = blockIdx.x / HW, h = blockIdx.x % HW;
    const int ch0 = blockIdx.y * 64;
    const int t = threadIdx.x;
#pragma unroll
    for (int j = 0; j < 4; ++j) {              // 896 float4 loads
        int idx = t + j * 256;
        if (idx >= 64 * 14) break;
        int c = idx / 14, f4 = idx % 14;
        float4 v = *(const float4*)&x[((b * CIN + ch0 + c) * HW + h) * HW + f4 * 4];
        tile[c][f4 * 4 + 0] = v.x; tile[c][f4 * 4 + 1] = v.y;
        tile[c][f4 * 4 + 2] = v.z; tile[c][f4 * 4 + 3] = v.w;
    }
    __syncthreads();
#pragma unroll
    for (int j = 0; j < 2; ++j) {              // 448 = 8 chunks * 56 w, w-major
        int i = t + j * 256;
        if (i >= HW * 8) break;
        int chunk = i / HW, w = i % HW;
        int c0 = chunk * 8;
        uint4 vv;
        unsigned* pv = (unsigned*)&vv;
#pragma unroll
        for (int k = 0; k < 4; ++k) {
            float q0 = rintf(tile[c0 + 2 * k][w] * 255.0f);
            float q1 = rintf(tile[c0 + 2 * k + 1][w] * 255.0f);
            q0 = fminf(fmaxf(q0, 0.0f), 255.0f);
            q1 = fminf(fmaxf(q1, 0.0f), 255.0f);
            __half2 h2 = __floats2half2_rn(q0, q1);
            pv[k] = *(unsigned*)&h2;
        }
        *(uint4*)&g_xh[((b * HW + h) * HW + w) * CIN + ch0 + c0] = vv;
    }
}

// ---------------------------------------------------------------------------
// Kernel 2: pcilt[...,1] -> [tap][o][c] fp16
// ---------------------------------------------------------------------------
__global__ void pack_w_kernel(const float* __restrict__ pcilt) {
    int idx = blockIdx.x * 256 + threadIdx.x;
    if (idx >= 9 * COUT * CIN) return;
    int c   = idx % CIN;
    int o   = (idx / CIN) % COUT;
    int tap = idx / (CIN * COUT);
    long long p = (((long long)(o * CIN + c)) * 9 + tap) * 256 + 1;
    g_wh[(tap * COUT + o) * CIN + c] = __float2half_rn(pcilt[p]);
}

// ---------------------------------------------------------------------------
// Kernel 3: fp16 HMMA implicit-GEMM conv. CTA = M128 (2 out rows) x N64,
// 8 warps of 32x32, 2-slot mbarrier W ring, 105KB smem -> 2 CTAs/SM.
// ---------------------------------------------------------------------------
#define SX_STRIDE 272
#define SX_ROWS   258
#define SW_STRIDE 272
#define SMEM_SX   0
#define SMEM_W0   (SX_ROWS * SX_STRIDE)            // 70176
#define W_SLOT_SZ (64 * SW_STRIDE)                 // 17408
#define SMEM_MB   (SMEM_W0 + 2 * W_SLOT_SZ)        // 104992
#define SMEM_SZ   (SMEM_MB + 64)                   // 105056
#define OSTR      132

__device__ __forceinline__ void hmma(float* c, unsigned a0, unsigned a1, unsigned a2, unsigned a3,
                                     unsigned b0, unsigned b1) {
    asm volatile(
        "mma.sync.aligned.m16n8k16.row.col.f32.f16.f16.f32 "
        "{%0,%1,%2,%3}, {%4,%5,%6,%7}, {%8,%9}, {%0,%1,%2,%3};"
        : "+f"(c[0]), "+f"(c[1]), "+f"(c[2]), "+f"(c[3])
        : "r"(a0), "r"(a1), "r"(a2), "r"(a3), "r"(b0), "r"(b1));
}
#define LDSM4(r0, r1, r2, r3, addr) \
    asm volatile("ldmatrix.sync.aligned.m8n8.x4.shared.b16 {%0,%1,%2,%3}, [%4];" \
        : "=r"(r0), "=r"(r1), "=r"(r2), "=r"(r3) : "r"(addr))
#define CPASYNC(dst, src, sz) \
    asm volatile("cp.async.cg.shared.global [%0], [%1], 16, %2;" :: "r"(dst), "l"(src), "r"(sz))
#define MBAR_INIT(a, n) asm volatile("mbarrier.init.shared.b64 [%0], %1;" :: "r"(a), "r"(n) : "memory")
#define MBAR_ARRIVE(a)  asm volatile("mbarrier.arrive.shared.b64 _, [%0];" :: "r"(a) : "memory")
#define CP_MBAR_ARRIVE(a) \
    asm volatile("cp.async.mbarrier.arrive.noinc.shared.b64 [%0];" :: "r"(a) : "memory")
#define MBAR_WAIT(a, ph) do {                                                     \
    uint32_t _m = (a), _p = (uint32_t)(ph), _d;                                   \
    asm volatile("{ .reg .pred p; mbarrier.try_wait.parity.acquire.cta.shared::cta.b64 p, [%1], %2; selp.b32 %0,1,0,p; }" \
        : "=r"(_d) : "r"(_m), "r"(_p) : "memory");                                \
    if (!_d) {                                                                    \
        asm volatile("{ .reg .pred P1; WL_%=: mbarrier.try_wait.parity.acquire.cta.shared::cta.b64 P1, [%0], %1, 0x989680;" \
            " @P1 bra.uni WD_%=; bra.uni WL_%=; WD_%=: }" :: "r"(_m), "r"(_p) : "memory"); \
    } } while (0)

__global__ void __launch_bounds__(256, 2)
conv_hmma_kernel(const float* __restrict__ bias, float* __restrict__ out) {
    extern __shared__ __align__(16) unsigned char smem[];
    const uint32_t sb = smem_u32(smem);

    const int t    = threadIdx.x;
    const int wid  = t >> 5;
    const int lane = t & 31;
    const int ocbase = blockIdx.x * 64;       // oc fastest: 4 sharers of A adjacent
    const int h0     = blockIdx.y * 2;
    const int b      = blockIdx.z;

    const uint32_t mb_full  = sb + SMEM_MB;        // 2 x 8B
    const uint32_t mb_empty = sb + SMEM_MB + 16;   // 2 x 8B

    if (t == 0) {
#pragma unroll
        for (int s = 0; s < 2; ++s) {
            MBAR_INIT(mb_full + s * 8, 256);
            MBAR_INIT(mb_empty + s * 8, 256);
        }
    }
    __syncthreads();

    // ---- Prologue: A tile + W taps 0,1 into slots 0,1 ----
    for (int i = t; i < SX_ROWS * 16; i += 256) {
        int pixel = i >> 4, chunk = i & 15;
        int irow = pixel >> 6, col = pixel & 63;
        int h_in = h0 + irow - 1, w_in = col - 1;
        bool ok = (pixel < 256) && (h_in >= 0) && (h_in < HW) && (w_in >= 0) && (w_in < HW);
        const __half* src = ok ? &g_xh[((b * HW + h_in) * HW + w_in) * CIN + chunk * 8] : g_xh;
        CPASYNC(sb + SMEM_SX + pixel * SX_STRIDE + chunk * 16, src, ok ? 16 : 0);
    }
#pragma unroll
    for (int tap = 0; tap < 2; ++tap) {
        uint32_t wdst = sb + SMEM_W0 + tap * W_SLOT_SZ;
#pragma unroll
        for (int j = 0; j < 4; ++j) {
            int i = t + j * 256;
            int o = i >> 4, chunk = i & 15;
            CPASYNC(wdst + o * SW_STRIDE + chunk * 16,
                    &g_wh[(tap * COUT + ocbase + o) * CIN + chunk * 8], 16);
        }
        CP_MBAR_ARRIVE(mb_full + tap * 8);
    }

    const int wm = (wid >> 1) * 32;          // 4 M-blocks of 32 rows
    const int wn = (wid & 1) * 32;           // 2 N-blocks of 32 oc

    float acc[2][4][4];
#pragma unroll
    for (int mt = 0; mt < 2; ++mt)
#pragma unroll
        for (int nt = 0; nt < 4; ++nt)
#pragma unroll
            for (int k = 0; k < 4; ++k) acc[mt][nt][k] = 0.0f;

    const int g = lane >> 3;
    const int a_lane = (((g & 1) * 8) + (lane & 7)) * SX_STRIDE + (g >> 1) * 16;
    const int b_lane = (((g >> 1) * 8) + (lane & 7)) * SW_STRIDE + (g & 1) * 16;

#pragma unroll 1
    for (int tap = 0; tap < 9; ++tap) {
        const int kh = tap / 3, kw = tap % 3;
        const int slot = tap & 1;
        const uint32_t swc = sb + SMEM_W0 + slot * W_SLOT_SZ;
        const uint32_t abase = sb + SMEM_SX + (kh * 64 + kw + wm) * SX_STRIDE + a_lane;
        const uint32_t bbase = swc + wn * SW_STRIDE + b_lane;

        MBAR_WAIT(mb_full + slot * 8, (tap >> 1) & 1);

#pragma unroll
        for (int ks = 0; ks < 8; ++ks) {
            const int koff = ks * 32;
            unsigned a[2][4], bf[4][2];
            LDSM4(a[0][0], a[0][1], a[0][2], a[0][3], abase + koff);
            LDSM4(a[1][0], a[1][1], a[1][2], a[1][3], abase + 16 * SX_STRIDE + koff);
            LDSM4(bf[0][0], bf[0][1], bf[1][0], bf[1][1], bbase + koff);
            LDSM4(bf[2][0], bf[2][1], bf[3][0], bf[3][1], bbase + 16 * SW_STRIDE + koff);
#pragma unroll
            for (int mt = 0; mt < 2; ++mt)
#pragma unroll
                for (int nt = 0; nt < 4; ++nt)
                    hmma(acc[mt][nt], a[mt][0], a[mt][1], a[mt][2], a[mt][3],
                         bf[nt][0], bf[nt][1]);
        }

        MBAR_ARRIVE(mb_empty + slot * 8);

        // Prefetch tap+2 into the slot just consumed
        if (tap <= 6) {
            MBAR_WAIT(mb_empty + slot * 8, (tap >> 1) & 1);
            uint32_t wdst = sb + SMEM_W0 + slot * W_SLOT_SZ;
#pragma unroll
            for (int j = 0; j < 4; ++j) {
                int i = t + j * 256;
                int o = i >> 4, chunk = i & 15;
                CPASYNC(wdst + o * SW_STRIDE + chunk * 16,
                        &g_wh[((tap + 2) * COUT + ocbase + o) * CIN + chunk * 8], 16);
            }
            CP_MBAR_ARRIVE(mb_full + slot * 8);
        }
    }

    __syncthreads();   // all warps done with A region before epilogue reuse

    // ---- Epilogue: transpose via smem -> coalesced NCHW float4 stores ----
    float* s_out = (float*)smem;    // [64 oc][OSTR], reuses A region
#pragma unroll
    for (int mt = 0; mt < 2; ++mt)
#pragma unroll
        for (int nt = 0; nt < 4; ++nt) {
            int row = wm + mt * 16 + (lane >> 2);
            int col = wn + nt * 8 + (lane & 3) * 2;
            s_out[col * OSTR + row]           = acc[mt][nt][0];
            s_out[(col + 1) * OSTR + row]     = acc[mt][nt][1];
            s_out[col * OSTR + row + 8]       = acc[mt][nt][2];
            s_out[(col + 1) * OSTR + row + 8] = acc[mt][nt][3];
        }
    __syncthreads();

#pragma unroll
    for (int j = 0; j < 7; ++j) {
        int i = t + j * 256;                 // 1792 = 64oc * 2rows * 14 float4
        int chunk = i % 14;
        int r     = (i / 14) & 1;
        int oc    = i / 28;
        const float* sp = &s_out[oc * OSTR + r * 64 + chunk * 4];
        float bv = bias[ocbase + oc];
        float4 v = make_float4(sp[0] + bv, sp[1] + bv, sp[2] + bv, sp[3] + bv);
        float* dst = out + (((long long)b * COUT + ocbase + oc) * HW + (h0 + r)) * HW + chunk * 4;
        *(float4*)dst = v;
    }
}

// ---------------------------------------------------------------------------
extern "C" void kernel_launch(void* const* d_in, const int* in_sizes, int n_in,
                              void* d_out, int out_size) {
    const float* x = nullptr;
    const float* pcilt = nullptr;
    const float* bias = nullptr;
    for (int i = 0; i < n_in; ++i) {
        if (in_sizes[i] == COUT) bias = (const float*)d_in[i];
        else if (in_sizes[i] == BATCH * CIN * HW * HW) x = (const float*)d_in[i];
        else pcilt = (const float*)d_in[i];
    }
    float* out = (float*)d_out;

    {
        dim3 g(BATCH * HW, 2);
        pack_x_kernel<<<g, 256>>>(x);
    }
    {
        int n = 9 * COUT * CIN;
        pack_w_kernel<<<(n + 255) / 256, 256>>>(pcilt);
    }
    {
        cudaFuncSetAttribute(conv_hmma_kernel,
                             cudaFuncAttributeMaxDynamicSharedMemorySize, SMEM_SZ);
        dim3 grid(COUT / 64, HW / 2, BATCH);   // (4, 28, 16) = 1792 CTAs
        conv_hmma_kernel<<<grid, 256, SMEM_SZ>>>(bias, out);
    }
    (void)out_size;
}